// round 9
// baseline (speedup 1.0000x reference)
#include <cuda_runtime.h>

// Problem constants (fixed by the reference: B=4, C=8, H=W=1024, R=1 cross kernel, wrap pad)
constexpr int Hh = 1024;
constexpr int Ww = 1024;
constexpr int PLANE = Hh * Ww;          // 1,048,576
constexpr int KR = 4;                   // rows per CTA strip
constexpr int STRIPS = Hh / KR;         // 256

// Accurate fp32 exp (Cody-Waite reduction + cephes degree-6 poly, ~1 ulp).
__device__ __forceinline__ float exp_acc(float x) {
    x = fminf(fmaxf(x, -87.3f), 88.0f);
    float n = rintf(x * 1.44269504088896341f);
    float r = fmaf(n, -0.693359375f, x);        // Cody-Waite hi
    r = fmaf(n, 2.12194440e-4f, r);             // Cody-Waite lo
    float rr = r * r;
    float y = 1.9875691500e-4f;
    y = fmaf(y, r, 1.3981999507e-3f);
    y = fmaf(y, r, 8.3334519073e-3f);
    y = fmaf(y, r, 4.1665795894e-2f);
    y = fmaf(y, r, 1.6666665459e-1f);
    y = fmaf(y, r, 5.0000001201e-1f);
    y = fmaf(y, rr, r);
    y = y + 1.0f;
    float sc = __int_as_float(((int)n + 127) << 23);
    return y * sc;
}

__device__ __forceinline__ float flip_one(float s, float J, float bf, float r, bool drop) {
    float de = 2.0f * s * J;
    bool flip;
    if (de <= 0.0f) {
        flip = drop;                            // p = 1, rand in [0,1) < 1 always
    } else {
        float p = exp_acc(-de * bf);
        flip = (r < p) && drop;
    }
    return flip ? -s : s;
}

__device__ __forceinline__ float4 ld4(const float* p) {
    return *reinterpret_cast<const float4*>(p);
}
__device__ __forceinline__ float4 ld_cs4(const float* p) {
    return __ldcs(reinterpret_cast<const float4*>(p));
}

// J(h,w) = S(h-1,w)+S(h+1,w)+S(h,w-1)+S(h,w+1), S = sum_c s_c (cross kernel,
// one output channel). One CTA = (batch, 4-row strip); 256 threads = full row,
// walking down with a 4-slot rolling S ring in smem (16 KB). One barrier per
// row: with 4 slots, the fastest warp's next STS (slot (i+3)&3) is disjoint
// from the slowest warp's reads (slots i..i+2 &3).
__global__ __launch_bounds__(256, 6) void ising_step_kernel(
    const float* __restrict__ x,      // (4, 9, 1024, 1024): s = ch 0..7, b = ch 8
    const float* __restrict__ rnd,    // (4, 8, 1024, 1024)
    const float* __restrict__ drop,   // (1024, 1024)
    float* __restrict__ out)          // (4, 9, 1024, 1024)
{
    __shared__ float S[4][Ww];        // S row (h0+j) lives in slot (j+1)&3

    int b     = blockIdx.x >> 8;                 // 4 batches
    int strip = blockIdx.x & (STRIPS - 1);
    int h0    = strip * KR;
    int w     = threadIdx.x * 4;
    int wl    = (w + Ww - 1) & (Ww - 1);         // left-of-pixel-0 (row wrap, in-block)
    int wr    = (w + 4) & (Ww - 1);              // right-of-pixel-3

    const float* xb = x + b * 9 * PLANE;
    const float* rb = rnd + b * 8 * PLANE;
    float* ob = out + b * 9 * PLANE;

    // Prologue: S(h0-1) -> slot 0, S(h0) -> slot 1. Same summation order as R8.
    #pragma unroll
    for (int j = 0; j < 2; j++) {
        int h = (h0 + Hh - 1 + j) & (Hh - 1);
        const float* sp = xb + h * Ww + w;
        float4 s4 = ld4(sp);
        #pragma unroll
        for (int c = 1; c < 8; c++) {
            float4 v = ld4(sp + c * PLANE);
            s4.x += v.x; s4.y += v.y; s4.z += v.z; s4.w += v.w;
        }
        *reinterpret_cast<float4*>(&S[j][w]) = s4;
    }

    #pragma unroll 1
    for (int i = 0; i < KR; i++) {
        int hc = h0 + i;                          // output row (h0+i <= 1023, no wrap)
        int hn = (hc + 1) & (Hh - 1);             // next row for S (wraps at strip end)

        // Phase 1: load next row's 8 channels (independent DRAM misses), sum to S.
        const float* spn = xb + hn * Ww + w;
        float4 s4 = ld4(spn);
        #pragma unroll
        for (int c = 1; c < 8; c++) {
            float4 v = ld4(spn + c * PLANE);
            s4.x += v.x; s4.y += v.y; s4.z += v.z; s4.w += v.w;
        }
        *reinterpret_cast<float4*>(&S[(i + 2) & 3][w]) = s4;
        __syncthreads();                          // S(hn) visible; single barrier per row

        // Phase 2: J for row hc from the 3 S rows in smem.
        const float* Su = S[i & 3];               // S(hc-1)
        const float* Sc = S[(i + 1) & 3];         // S(hc)
        const float* Sd = S[(i + 2) & 3];         // S(hc+1)
        float4 su = *reinterpret_cast<const float4*>(&Su[w]);
        float4 sc = *reinterpret_cast<const float4*>(&Sc[w]);
        float4 sd = *reinterpret_cast<const float4*>(&Sd[w]);
        float lf = Sc[wl], rt = Sc[wr];
        float4 J;
        J.x = (su.x + sd.x) + (lf   + sc.y);
        J.y = (su.y + sd.y) + (sc.x + sc.z);
        J.z = (su.z + sd.z) + (sc.y + sc.w);
        J.w = (su.w + sd.w) + (sc.z + rt);

        // Phase 3: flips for row hc.
        int rowc = hc * Ww + w;
        float4 bf = ld4(xb + 8 * PLANE + rowc);
        float4 dv = ld4(drop + rowc);
        bool d0 = dv.x > 0.5f, d1 = dv.y > 0.5f, d2 = dv.z > 0.5f, d3 = dv.w > 0.5f;
        *reinterpret_cast<float4*>(ob + 8 * PLANE + rowc) = bf;   // pass-through field

        #pragma unroll
        for (int c = 0; c < 8; c++) {
            float4 cc = ld4(xb + c * PLANE + rowc);   // loaded last iteration -> L1/L2 hit
            float4 rv = ld_cs4(rb + c * PLANE + rowc);// read-once stream
            float4 o;
            o.x = flip_one(cc.x, J.x, bf.x, rv.x, d0);
            o.y = flip_one(cc.y, J.y, bf.y, rv.y, d1);
            o.z = flip_one(cc.z, J.z, bf.z, rv.z, d2);
            o.w = flip_one(cc.w, J.w, bf.w, rv.w, d3);
            *reinterpret_cast<float4*>(ob + c * PLANE + rowc) = o;
        }
    }
}

extern "C" void kernel_launch(void* const* d_in, const int* in_sizes, int n_in,
                              void* d_out, int out_size) {
    const float* x    = (const float*)d_in[0];   // (4,9,1024,1024)
    const float* rnd  = (const float*)d_in[1];   // (4,8,1024,1024)
    const float* drop = (const float*)d_in[2];   // (1024,1024)
    // d_in[3] = nn_kernel: fixed cross structure, baked into the kernel
    float* out = (float*)d_out;

    int grid = 4 * STRIPS;                       // 1024 CTAs
    ising_step_kernel<<<grid, 256>>>(x, rnd, drop, out);
}

// round 11
// speedup vs baseline: 1.2095x; 1.2095x over previous
#include <cuda_runtime.h>
#include <cstdint>

// Problem constants (fixed by the reference: B=4, C=8, H=W=1024, R=1 cross kernel, wrap pad)
constexpr int Hh = 1024;
constexpr int Ww = 1024;
constexpr int PLANE = Hh * Ww;          // 1,048,576
constexpr int KR = 8;                   // rows per CTA strip
constexpr int STRIPS = Hh / KR;         // 128

// Accurate fp32 exp (Cody-Waite reduction + cephes degree-6 poly, ~1 ulp).
__device__ __forceinline__ float exp_acc(float x) {
    x = fminf(fmaxf(x, -87.3f), 88.0f);
    float n = rintf(x * 1.44269504088896341f);
    float r = fmaf(n, -0.693359375f, x);        // Cody-Waite hi
    r = fmaf(n, 2.12194440e-4f, r);             // Cody-Waite lo
    float rr = r * r;
    float y = 1.9875691500e-4f;
    y = fmaf(y, r, 1.3981999507e-3f);
    y = fmaf(y, r, 8.3334519073e-3f);
    y = fmaf(y, r, 4.1665795894e-2f);
    y = fmaf(y, r, 1.6666665459e-1f);
    y = fmaf(y, r, 5.0000001201e-1f);
    y = fmaf(y, rr, r);
    y = y + 1.0f;
    float sc = __int_as_float(((int)n + 127) << 23);
    return y * sc;
}

__device__ __forceinline__ float flip_one(float s, float J, float bf, float r, bool drop) {
    float de = 2.0f * s * J;
    bool flip;
    if (de <= 0.0f) {
        flip = drop;                            // p = 1, rand in [0,1) < 1 always
    } else {
        float p = exp_acc(-de * bf);
        flip = (r < p) && drop;
    }
    return flip ? -s : s;
}

__device__ __forceinline__ float4 ld4(const float* p) {
    return *reinterpret_cast<const float4*>(p);
}

__device__ __forceinline__ void cp_async16(unsigned int smem_addr, const float* gmem) {
    asm volatile("cp.async.cg.shared.global [%0], [%1], 16;\n"
                 :: "r"(smem_addr), "l"(gmem) : "memory");
}
__device__ __forceinline__ void cp_async_commit() {
    asm volatile("cp.async.commit_group;\n" ::: "memory");
}
__device__ __forceinline__ void cp_async_wait0() {
    asm volatile("cp.async.wait_group 0;\n" ::: "memory");
}

// J(h,w) = S(h-1,w)+S(h+1,w)+S(h,w-1)+S(h,w+1), S = sum_c s_c (cross kernel,
// one output channel). One CTA = (batch, 8-row strip); 256 threads = full row,
// rolling 4-slot S ring (one barrier per row). The key change vs R8: rand for
// the current row is fetched via cp.async.cg into thread-private smem slots,
// issued at the TOP of the iteration alongside the s-next LDGs, so all 16
// DRAM misses per thread per row overlap in a single batch (the compiler
// cannot hoist LDGs across __syncthreads, cp.async sidesteps that).
__global__ __launch_bounds__(256, 4) void ising_step_kernel(
    const float* __restrict__ x,      // (4, 9, 1024, 1024): s = ch 0..7, b = ch 8
    const float* __restrict__ rnd,    // (4, 8, 1024, 1024)
    const float* __restrict__ drop,   // (1024, 1024)
    float* __restrict__ out)          // (4, 9, 1024, 1024)
{
    __shared__ float S[4][Ww];        // S row (h0+j) lives in slot (j+1)&3
    __shared__ float rsm[8][Ww];      // rand row staging (thread-private 16B slots)

    int b     = blockIdx.x >> 7;                 // 4 batches
    int strip = blockIdx.x & (STRIPS - 1);
    int h0    = strip * KR;
    int w     = threadIdx.x * 4;
    int wl    = (w + Ww - 1) & (Ww - 1);         // left-of-pixel-0 (row wrap, in-block)
    int wr    = (w + 4) & (Ww - 1);              // right-of-pixel-3

    const float* xb = x + b * 9 * PLANE;
    const float* rb = rnd + b * 8 * PLANE;
    float* ob = out + b * 9 * PLANE;

    unsigned int rsm_base = (unsigned int)__cvta_generic_to_shared(&rsm[0][w]);

    // Prologue: S(h0-1) -> slot 0, S(h0) -> slot 1. Summation order identical to R8.
    #pragma unroll
    for (int j = 0; j < 2; j++) {
        int h = (h0 + Hh - 1 + j) & (Hh - 1);
        const float* sp = xb + h * Ww + w;
        float4 cv[8];
        #pragma unroll
        for (int c = 0; c < 8; c++) cv[c] = ld4(sp + c * PLANE);
        float4 s4 = make_float4(0.f, 0.f, 0.f, 0.f);
        #pragma unroll
        for (int c = 0; c < 8; c++) {
            s4.x += cv[c].x; s4.y += cv[c].y; s4.z += cv[c].z; s4.w += cv[c].w;
        }
        *reinterpret_cast<float4*>(&S[j][w]) = s4;
    }

    #pragma unroll 1
    for (int i = 0; i < KR; i++) {
        int hc = h0 + i;                          // output row (h0+i <= 1023, no wrap)
        int hn = (hc + 1) & (Hh - 1);             // next row for S (wraps at strip end)
        int rowc = hc * Ww + w;

        // ---- Single miss batch: rand(hc) via cp.async + s(hn) via LDG ----
        {
            const float* rp = rb + rowc;
            #pragma unroll
            for (int c = 0; c < 8; c++)
                cp_async16(rsm_base + c * (Ww * 4), rp + c * PLANE);
            cp_async_commit();
        }
        const float* spn = xb + hn * Ww + w;
        float4 cv[8];
        #pragma unroll
        for (int c = 0; c < 8; c++) cv[c] = ld4(spn + c * PLANE);
        float4 s4 = make_float4(0.f, 0.f, 0.f, 0.f);
        #pragma unroll
        for (int c = 0; c < 8; c++) {
            s4.x += cv[c].x; s4.y += cv[c].y; s4.z += cv[c].z; s4.w += cv[c].w;
        }
        *reinterpret_cast<float4*>(&S[(i + 2) & 3][w]) = s4;
        __syncthreads();                          // S(hn) visible; single barrier per row

        // ---- J for row hc from the 3 S rows in smem ----
        const float* Su = S[i & 3];               // S(hc-1)
        const float* Sc = S[(i + 1) & 3];         // S(hc)
        const float* Sd = S[(i + 2) & 3];         // S(hc+1)
        float4 su = *reinterpret_cast<const float4*>(&Su[w]);
        float4 sc = *reinterpret_cast<const float4*>(&Sc[w]);
        float4 sd = *reinterpret_cast<const float4*>(&Sd[w]);
        float lf = Sc[wl], rt = Sc[wr];
        float4 J;
        J.x = (su.x + sd.x) + (lf   + sc.y);
        J.y = (su.y + sd.y) + (sc.x + sc.z);
        J.z = (su.z + sd.z) + (sc.y + sc.w);
        J.w = (su.w + sd.w) + (sc.z + rt);

        // ---- Flips for row hc ----
        float4 bf = ld4(xb + 8 * PLANE + rowc);
        float4 dv = ld4(drop + rowc);
        bool d0 = dv.x > 0.5f, d1 = dv.y > 0.5f, d2 = dv.z > 0.5f, d3 = dv.w > 0.5f;
        *reinterpret_cast<float4*>(ob + 8 * PLANE + rowc) = bf;   // pass-through field

        cp_async_wait0();                         // own rand slots ready (self-read: no barrier)

        #pragma unroll
        for (int c = 0; c < 8; c++) {
            float4 cc = ld4(xb + c * PLANE + rowc);        // loaded last iteration -> cache hit
            float4 rv = *reinterpret_cast<const float4*>(&rsm[c][w]);
            float4 o;
            o.x = flip_one(cc.x, J.x, bf.x, rv.x, d0);
            o.y = flip_one(cc.y, J.y, bf.y, rv.y, d1);
            o.z = flip_one(cc.z, J.z, bf.z, rv.z, d2);
            o.w = flip_one(cc.w, J.w, bf.w, rv.w, d3);
            *reinterpret_cast<float4*>(ob + c * PLANE + rowc) = o;
        }
    }
}

extern "C" void kernel_launch(void* const* d_in, const int* in_sizes, int n_in,
                              void* d_out, int out_size) {
    const float* x    = (const float*)d_in[0];   // (4,9,1024,1024)
    const float* rnd  = (const float*)d_in[1];   // (4,8,1024,1024)
    const float* drop = (const float*)d_in[2];   // (1024,1024)
    // d_in[3] = nn_kernel: fixed cross structure, baked into the kernel
    float* out = (float*)d_out;

    int grid = 4 * STRIPS;                       // 512 CTAs: all resident, single wave
    ising_step_kernel<<<grid, 256>>>(x, rnd, drop, out);
}

// round 12
// speedup vs baseline: 1.2369x; 1.0226x over previous
#include <cuda_runtime.h>
#include <cstdint>

// Problem constants (fixed by the reference: B=4, C=8, H=W=1024, R=1 cross kernel, wrap pad)
constexpr int Hh = 1024;
constexpr int Ww = 1024;
constexpr int PLANE = Hh * Ww;          // 1,048,576
constexpr int KR = 8;                   // rows per CTA strip
constexpr int STRIPS = Hh / KR;         // 128

// Accurate fp32 exp (Cody-Waite reduction + cephes degree-6 poly, ~1 ulp).
__device__ __forceinline__ float exp_acc(float x) {
    x = fminf(fmaxf(x, -87.3f), 88.0f);
    float n = rintf(x * 1.44269504088896341f);
    float r = fmaf(n, -0.693359375f, x);        // Cody-Waite hi
    r = fmaf(n, 2.12194440e-4f, r);             // Cody-Waite lo
    float rr = r * r;
    float y = 1.9875691500e-4f;
    y = fmaf(y, r, 1.3981999507e-3f);
    y = fmaf(y, r, 8.3334519073e-3f);
    y = fmaf(y, r, 4.1665795894e-2f);
    y = fmaf(y, r, 1.6666665459e-1f);
    y = fmaf(y, r, 5.0000001201e-1f);
    y = fmaf(y, rr, r);
    y = y + 1.0f;
    float sc = __int_as_float(((int)n + 127) << 23);
    return y * sc;
}

__device__ __forceinline__ float flip_one(float s, float J, float bf, float r, bool drop) {
    float de = 2.0f * s * J;
    bool flip;
    if (de <= 0.0f) {
        flip = drop;                            // p = 1, rand in [0,1) < 1 always
    } else {
        float p = exp_acc(-de * bf);
        flip = (r < p) && drop;
    }
    return flip ? -s : s;
}

__device__ __forceinline__ float4 ld4(const float* p) {
    return *reinterpret_cast<const float4*>(p);
}
__device__ __forceinline__ float4 ld_cs4(const float* p) {
    return __ldcs(reinterpret_cast<const float4*>(p));
}

// J(h,w) = S(h-1,w)+S(h+1,w)+S(h,w-1)+S(h,w+1), S = sum_c s_c (cross kernel,
// one output channel). One CTA = (batch, 8-row strip); 256 threads = full row,
// rolling 4-slot S ring in smem (16 KB total -> L1 keeps ~212 KB).
// Single DRAM miss batch per row: the 8 rand loads for row hc are issued into
// REGISTERS before __syncthreads (ptxas does not move loads across BAR), so
// they overlap the 8 s(hn) loads; consumers run after the barrier.
__global__ __launch_bounds__(256, 4) void ising_step_kernel(
    const float* __restrict__ x,      // (4, 9, 1024, 1024): s = ch 0..7, b = ch 8
    const float* __restrict__ rnd,    // (4, 8, 1024, 1024)
    const float* __restrict__ drop,   // (1024, 1024)
    float* __restrict__ out)          // (4, 9, 1024, 1024)
{
    __shared__ float S[4][Ww];        // S row (h0+j) lives in slot (j+1)&3

    int b     = blockIdx.x >> 7;                 // 4 batches
    int strip = blockIdx.x & (STRIPS - 1);
    int h0    = strip * KR;
    int w     = threadIdx.x * 4;
    int wl    = (w + Ww - 1) & (Ww - 1);         // left-of-pixel-0 (row wrap, in-block)
    int wr    = (w + 4) & (Ww - 1);              // right-of-pixel-3

    const float* xb = x + b * 9 * PLANE;
    const float* rb = rnd + b * 8 * PLANE;
    float* ob = out + b * 9 * PLANE;

    // Prologue: S(h0-1) -> slot 0, S(h0) -> slot 1. Summation order identical to R8.
    #pragma unroll
    for (int j = 0; j < 2; j++) {
        int h = (h0 + Hh - 1 + j) & (Hh - 1);
        const float* sp = xb + h * Ww + w;
        float4 cv[8];
        #pragma unroll
        for (int c = 0; c < 8; c++) cv[c] = ld4(sp + c * PLANE);
        float4 s4 = make_float4(0.f, 0.f, 0.f, 0.f);
        #pragma unroll
        for (int c = 0; c < 8; c++) {
            s4.x += cv[c].x; s4.y += cv[c].y; s4.z += cv[c].z; s4.w += cv[c].w;
        }
        *reinterpret_cast<float4*>(&S[j][w]) = s4;
    }

    #pragma unroll 1
    for (int i = 0; i < KR; i++) {
        int hc = h0 + i;                          // output row (h0+i <= 1023, no wrap)
        int hn = (hc + 1) & (Hh - 1);             // next row for S (wraps at strip end)
        int rowc = hc * Ww + w;

        // ---- Single miss batch, all pre-barrier ----
        // rand(hc) into registers (consumed post-barrier in phase 3)
        float4 rv[8];
        {
            const float* rp = rb + rowc;
            #pragma unroll
            for (int c = 0; c < 8; c++) rv[c] = ld_cs4(rp + c * PLANE);
        }
        // s(hn) for the next S row
        const float* spn = xb + hn * Ww + w;
        float4 cv[8];
        #pragma unroll
        for (int c = 0; c < 8; c++) cv[c] = ld4(spn + c * PLANE);
        float4 s4 = make_float4(0.f, 0.f, 0.f, 0.f);
        #pragma unroll
        for (int c = 0; c < 8; c++) {
            s4.x += cv[c].x; s4.y += cv[c].y; s4.z += cv[c].z; s4.w += cv[c].w;
        }
        *reinterpret_cast<float4*>(&S[(i + 2) & 3][w]) = s4;
        __syncthreads();                          // S(hn) visible; single barrier per row

        // ---- J for row hc from the 3 S rows in smem ----
        const float* Su = S[i & 3];               // S(hc-1)
        const float* Sc = S[(i + 1) & 3];         // S(hc)
        const float* Sd = S[(i + 2) & 3];         // S(hc+1)
        float4 su = *reinterpret_cast<const float4*>(&Su[w]);
        float4 sc = *reinterpret_cast<const float4*>(&Sc[w]);
        float4 sd = *reinterpret_cast<const float4*>(&Sd[w]);
        float lf = Sc[wl], rt = Sc[wr];
        float4 J;
        J.x = (su.x + sd.x) + (lf   + sc.y);
        J.y = (su.y + sd.y) + (sc.x + sc.z);
        J.z = (su.z + sd.z) + (sc.y + sc.w);
        J.w = (su.w + sd.w) + (sc.z + rt);

        // ---- Flips for row hc ----
        float4 bf = ld4(xb + 8 * PLANE + rowc);
        float4 dv = ld4(drop + rowc);
        bool d0 = dv.x > 0.5f, d1 = dv.y > 0.5f, d2 = dv.z > 0.5f, d3 = dv.w > 0.5f;
        *reinterpret_cast<float4*>(ob + 8 * PLANE + rowc) = bf;   // pass-through field

        #pragma unroll
        for (int c = 0; c < 8; c++) {
            float4 cc = ld4(xb + c * PLANE + rowc);   // loaded last iteration -> L1 hit (L1 ~212 KB)
            float4 o;
            o.x = flip_one(cc.x, J.x, bf.x, rv[c].x, d0);
            o.y = flip_one(cc.y, J.y, bf.y, rv[c].y, d1);
            o.z = flip_one(cc.z, J.z, bf.z, rv[c].z, d2);
            o.w = flip_one(cc.w, J.w, bf.w, rv[c].w, d3);
            *reinterpret_cast<float4*>(ob + c * PLANE + rowc) = o;
        }
    }
}

extern "C" void kernel_launch(void* const* d_in, const int* in_sizes, int n_in,
                              void* d_out, int out_size) {
    const float* x    = (const float*)d_in[0];   // (4,9,1024,1024)
    const float* rnd  = (const float*)d_in[1];   // (4,8,1024,1024)
    const float* drop = (const float*)d_in[2];   // (1024,1024)
    // d_in[3] = nn_kernel: fixed cross structure, baked into the kernel
    float* out = (float*)d_out;

    int grid = 4 * STRIPS;                       // 512 CTAs
    ising_step_kernel<<<grid, 256>>>(x, rnd, drop, out);
}

// round 13
// speedup vs baseline: 1.2763x; 1.0319x over previous
#include <cuda_runtime.h>
#include <cstdint>

// Problem constants (fixed by the reference: B=4, C=8, H=W=1024, R=1 cross kernel, wrap pad)
constexpr int Hh = 1024;
constexpr int Ww = 1024;
constexpr int PLANE = Hh * Ww;          // 1,048,576
constexpr int NSM = 152;                // GB300 SM count: 4 CTAs/SM x 152 = single balanced wave
constexpr int STRIPS = NSM;             // strips per batch image

// Accurate fp32 exp (Cody-Waite reduction + cephes degree-6 poly, ~1 ulp).
__device__ __forceinline__ float exp_acc(float x) {
    x = fminf(fmaxf(x, -87.3f), 88.0f);
    float n = rintf(x * 1.44269504088896341f);
    float r = fmaf(n, -0.693359375f, x);        // Cody-Waite hi
    r = fmaf(n, 2.12194440e-4f, r);             // Cody-Waite lo
    float rr = r * r;
    float y = 1.9875691500e-4f;
    y = fmaf(y, r, 1.3981999507e-3f);
    y = fmaf(y, r, 8.3334519073e-3f);
    y = fmaf(y, r, 4.1665795894e-2f);
    y = fmaf(y, r, 1.6666665459e-1f);
    y = fmaf(y, r, 5.0000001201e-1f);
    y = fmaf(y, rr, r);
    y = y + 1.0f;
    float sc = __int_as_float(((int)n + 127) << 23);
    return y * sc;
}

__device__ __forceinline__ float flip_one(float s, float J, float bf, float r, bool drop) {
    float de = 2.0f * s * J;
    bool flip;
    if (de <= 0.0f) {
        flip = drop;                            // p = 1, rand in [0,1) < 1 always
    } else {
        float p = exp_acc(-de * bf);
        flip = (r < p) && drop;
    }
    return flip ? -s : s;
}

__device__ __forceinline__ float4 ld4(const float* p) {
    return *reinterpret_cast<const float4*>(p);
}
__device__ __forceinline__ float4 ld_cs4(const float* p) {
    return __ldcs(reinterpret_cast<const float4*>(p));
}

// J(h,w) = S(h-1,w)+S(h+1,w)+S(h,w-1)+S(h,w+1), S = sum_c s_c (cross kernel,
// one output channel). Grid = 4 batches x 152 strips = 608 CTAs = exactly
// 4 CTAs on each of the 152 SMs: single wave, no quantization tail (the
// structural waste shared by all previous 512-CTA variants). Each strip is
// 6-7 contiguous rows; 256 threads = full row; rolling 4-slot S ring in smem
// (16 KB -> L1 keeps ~212 KB); one barrier per row.
__global__ __launch_bounds__(256, 4) void ising_step_kernel(
    const float* __restrict__ x,      // (4, 9, 1024, 1024): s = ch 0..7, b = ch 8
    const float* __restrict__ rnd,    // (4, 8, 1024, 1024)
    const float* __restrict__ drop,   // (1024, 1024)
    float* __restrict__ out)          // (4, 9, 1024, 1024)
{
    __shared__ float S[4][Ww];        // S row (h_start+k) lives in slot (k+1)&3

    int j = blockIdx.x;               // 0..607
    int b = j >> 7 >> 2;              // placeholder (recomputed below)
    // Decompose: batch = j / STRIPS, strip = j % STRIPS
    b = j / STRIPS;
    int strip = j - b * STRIPS;
    int h_start = (strip * Hh) / STRIPS;
    int h_end   = ((strip + 1) * Hh) / STRIPS;   // 6 or 7 rows
    int w  = threadIdx.x * 4;
    int wl = (w + Ww - 1) & (Ww - 1);            // left-of-pixel-0 (row wrap, in-block)
    int wr = (w + 4) & (Ww - 1);                 // right-of-pixel-3

    const float* xb = x + b * 9 * PLANE;
    const float* rb = rnd + b * 8 * PLANE;
    float* ob = out + b * 9 * PLANE;

    // Prologue: S(h_start-1) -> slot 0, S(h_start) -> slot 1. Same summation order.
    #pragma unroll
    for (int p = 0; p < 2; p++) {
        int h = (h_start + Hh - 1 + p) & (Hh - 1);
        const float* sp = xb + h * Ww + w;
        float4 cv[8];
        #pragma unroll
        for (int c = 0; c < 8; c++) cv[c] = ld4(sp + c * PLANE);
        float4 s4 = make_float4(0.f, 0.f, 0.f, 0.f);
        #pragma unroll
        for (int c = 0; c < 8; c++) {
            s4.x += cv[c].x; s4.y += cv[c].y; s4.z += cv[c].z; s4.w += cv[c].w;
        }
        *reinterpret_cast<float4*>(&S[p][w]) = s4;
    }

    #pragma unroll 1
    for (int k = 0; k < h_end - h_start; k++) {
        int hc = h_start + k;                     // output row (< 1024, no wrap)
        int hn = (hc + 1) & (Hh - 1);             // next row for S (global wrap at 1023)
        int rowc = hc * Ww + w;

        // ---- Phase 1: load next row's 8 channels (one batched miss group), sum to S ----
        const float* spn = xb + hn * Ww + w;
        float4 cv[8];
        #pragma unroll
        for (int c = 0; c < 8; c++) cv[c] = ld4(spn + c * PLANE);
        float4 s4 = make_float4(0.f, 0.f, 0.f, 0.f);
        #pragma unroll
        for (int c = 0; c < 8; c++) {
            s4.x += cv[c].x; s4.y += cv[c].y; s4.z += cv[c].z; s4.w += cv[c].w;
        }
        *reinterpret_cast<float4*>(&S[(k + 2) & 3][w]) = s4;
        __syncthreads();                          // S(hn) visible; single barrier per row

        // ---- Phase 2: J for row hc from the 3 S rows in smem ----
        const float* Su = S[k & 3];               // S(hc-1)
        const float* Sc = S[(k + 1) & 3];         // S(hc)
        const float* Sd = S[(k + 2) & 3];         // S(hc+1)
        float4 su = *reinterpret_cast<const float4*>(&Su[w]);
        float4 sc = *reinterpret_cast<const float4*>(&Sc[w]);
        float4 sd = *reinterpret_cast<const float4*>(&Sd[w]);
        float lf = Sc[wl], rt = Sc[wr];
        float4 J;
        J.x = (su.x + sd.x) + (lf   + sc.y);
        J.y = (su.y + sd.y) + (sc.x + sc.z);
        J.z = (su.z + sd.z) + (sc.y + sc.w);
        J.w = (su.w + sd.w) + (sc.z + rt);

        // ---- Phase 3: flips for row hc ----
        float4 bf = ld4(xb + 8 * PLANE + rowc);
        float4 dv = ld4(drop + rowc);
        bool d0 = dv.x > 0.5f, d1 = dv.y > 0.5f, d2 = dv.z > 0.5f, d3 = dv.w > 0.5f;
        *reinterpret_cast<float4*>(ob + 8 * PLANE + rowc) = bf;   // pass-through field

        #pragma unroll
        for (int c = 0; c < 8; c++) {
            float4 cc = ld4(xb + c * PLANE + rowc);    // loaded last iteration -> L1 hit
            float4 rv = ld_cs4(rb + c * PLANE + rowc); // read-once stream
            float4 o;
            o.x = flip_one(cc.x, J.x, bf.x, rv.x, d0);
            o.y = flip_one(cc.y, J.y, bf.y, rv.y, d1);
            o.z = flip_one(cc.z, J.z, bf.z, rv.z, d2);
            o.w = flip_one(cc.w, J.w, bf.w, rv.w, d3);
            *reinterpret_cast<float4*>(ob + c * PLANE + rowc) = o;
        }
    }
}

extern "C" void kernel_launch(void* const* d_in, const int* in_sizes, int n_in,
                              void* d_out, int out_size) {
    const float* x    = (const float*)d_in[0];   // (4,9,1024,1024)
    const float* rnd  = (const float*)d_in[1];   // (4,8,1024,1024)
    const float* drop = (const float*)d_in[2];   // (1024,1024)
    // d_in[3] = nn_kernel: fixed cross structure, baked into the kernel
    float* out = (float*)d_out;

    int grid = 4 * STRIPS;                       // 608 CTAs = 4/SM x 152 SMs, single wave
    ising_step_kernel<<<grid, 256>>>(x, rnd, drop, out);
}

// round 14
// speedup vs baseline: 1.3133x; 1.0290x over previous
#include <cuda_runtime.h>
#include <cstdint>

// Problem constants (fixed by the reference: B=4, C=8, H=W=1024, R=1 cross kernel, wrap pad)
constexpr int Hh = 1024;
constexpr int Ww = 1024;
constexpr int PLANE = Hh * Ww;          // 1,048,576
constexpr int SPB = 76;                 // strips per batch: 4*76 = 304 CTAs = 2/SM x 152 SMs

// Accurate fp32 exp (Cody-Waite reduction + cephes degree-6 poly, ~1 ulp).
__device__ __forceinline__ float exp_acc(float x) {
    x = fminf(fmaxf(x, -87.3f), 88.0f);
    float n = rintf(x * 1.44269504088896341f);
    float r = fmaf(n, -0.693359375f, x);        // Cody-Waite hi
    r = fmaf(n, 2.12194440e-4f, r);             // Cody-Waite lo
    float rr = r * r;
    float y = 1.9875691500e-4f;
    y = fmaf(y, r, 1.3981999507e-3f);
    y = fmaf(y, r, 8.3334519073e-3f);
    y = fmaf(y, r, 4.1665795894e-2f);
    y = fmaf(y, r, 1.6666665459e-1f);
    y = fmaf(y, r, 5.0000001201e-1f);
    y = fmaf(y, rr, r);
    y = y + 1.0f;
    float sc = __int_as_float(((int)n + 127) << 23);
    return y * sc;
}

__device__ __forceinline__ float flip_one(float s, float J, float bf, float r, bool drop) {
    float de = 2.0f * s * J;
    bool flip;
    if (de <= 0.0f) {
        flip = drop;                            // p = 1, rand in [0,1) < 1 always
    } else {
        float p = exp_acc(-de * bf);
        flip = (r < p) && drop;
    }
    return flip ? -s : s;
}

__device__ __forceinline__ float4 ld4(const float* p) {
    return *reinterpret_cast<const float4*>(p);
}
__device__ __forceinline__ float4 ld_cs4(const float* p) {
    return __ldcs(reinterpret_cast<const float4*>(p));
}
__device__ __forceinline__ void st_cs4(float* p, float4 v) {
    __stcs(reinterpret_cast<float4*>(p), v);
}

// J(h,w) = S(h-1,w)+S(h+1,w)+S(h,w-1)+S(h,w+1), S = sum_c s_c (cross kernel,
// one output channel). 512-thread CTAs: half A (warps 0-7) owns row hc, half B
// (warps 8-15) owns row hc+1, processing 2 rows per iteration with ONE barrier.
// Grid = 4 batches x 76 strips = 304 CTAs = exactly 2 per SM (balanced single
// wave). Strips of ~13.5 rows amortize the 2-row S prologue (s read factor
// 1.30 -> 1.15). 6-slot rolling S ring in smem (24 KB); outputs stored .cs
// (write-once, keep L2 for s-row reuse).
__global__ __launch_bounds__(512, 2) void ising_step_kernel(
    const float* __restrict__ x,      // (4, 9, 1024, 1024): s = ch 0..7, b = ch 8
    const float* __restrict__ rnd,    // (4, 8, 1024, 1024)
    const float* __restrict__ drop,   // (1024, 1024)
    float* __restrict__ out)          // (4, 9, 1024, 1024)
{
    __shared__ float S[6][Ww];        // S row (h_start-1+j) lives in slot j%6

    int b     = blockIdx.x / SPB;
    int strip = blockIdx.x - b * SPB;
    int h_start = (strip * Hh) / SPB;
    int h_end   = ((strip + 1) * Hh) / SPB;      // 13 or 14 rows
    int half = threadIdx.x >> 8;                 // 0: row hc, 1: row hc+1
    int t    = threadIdx.x & 255;
    int w    = t * 4;
    int wl   = (w + Ww - 1) & (Ww - 1);          // left-of-pixel-0 (row wrap, in-block)
    int wr   = (w + 4) & (Ww - 1);               // right-of-pixel-3

    const float* xb = x + b * 9 * PLANE;
    const float* rb = rnd + b * 8 * PLANE;
    float* ob = out + b * 9 * PLANE;

    // Prologue: half A -> S(h_start-1) slot 0, half B -> S(h_start) slot 1.
    // Visibility is covered by the first in-loop barrier.
    {
        int h = (h_start + Hh - 1 + half) & (Hh - 1);
        const float* sp = xb + h * Ww + w;
        float4 cv[8];
        #pragma unroll
        for (int c = 0; c < 8; c++) cv[c] = ld4(sp + c * PLANE);
        float4 s4 = make_float4(0.f, 0.f, 0.f, 0.f);
        #pragma unroll
        for (int c = 0; c < 8; c++) {
            s4.x += cv[c].x; s4.y += cv[c].y; s4.z += cv[c].z; s4.w += cv[c].w;
        }
        *reinterpret_cast<float4*>(&S[half][w]) = s4;
    }

    int n = h_end - h_start;
    int npairs = (n + 1) >> 1;

    #pragma unroll 1
    for (int k = 0; k < npairs; k++) {
        // ---- Phase 1: each half loads one new S row (local j = 2+2k+half) ----
        {
            int hl = (h_start + 1 + 2 * k + half) & (Hh - 1);
            int slot = (2 + 2 * k + half) % 6;
            const float* sp = xb + hl * Ww + w;
            float4 cv[8];
            #pragma unroll
            for (int c = 0; c < 8; c++) cv[c] = ld4(sp + c * PLANE);
            float4 s4 = make_float4(0.f, 0.f, 0.f, 0.f);
            #pragma unroll
            for (int c = 0; c < 8; c++) {
                s4.x += cv[c].x; s4.y += cv[c].y; s4.z += cv[c].z; s4.w += cv[c].w;
            }
            *reinterpret_cast<float4*>(&S[slot][w]) = s4;
        }
        __syncthreads();                         // one barrier per TWO output rows

        // ---- Phases 2+3: my output row hc = h_start + 2k + half ----
        int hc = h_start + 2 * k + half;
        if (hc < h_end) {                        // odd-n tail: half B idles (post-barrier: safe)
            int jc = 1 + 2 * k + half;           // local index of row hc
            const float* Su = S[(jc - 1) % 6];   // S(hc-1)
            const float* Sc = S[jc % 6];         // S(hc)
            const float* Sd = S[(jc + 1) % 6];   // S(hc+1)
            float4 su = *reinterpret_cast<const float4*>(&Su[w]);
            float4 sc = *reinterpret_cast<const float4*>(&Sc[w]);
            float4 sd = *reinterpret_cast<const float4*>(&Sd[w]);
            float lf = Sc[wl], rt = Sc[wr];
            float4 J;
            J.x = (su.x + sd.x) + (lf   + sc.y);
            J.y = (su.y + sd.y) + (sc.x + sc.z);
            J.z = (su.z + sd.z) + (sc.y + sc.w);
            J.w = (su.w + sd.w) + (sc.z + rt);

            int rowc = hc * Ww + w;
            float4 bf = ld4(xb + 8 * PLANE + rowc);
            float4 dv = ld4(drop + rowc);
            bool d0 = dv.x > 0.5f, d1 = dv.y > 0.5f, d2 = dv.z > 0.5f, d3 = dv.w > 0.5f;
            st_cs4(ob + 8 * PLANE + rowc, bf);   // pass-through field (write-once)

            #pragma unroll
            for (int c = 0; c < 8; c++) {
                float4 cc = ld4(xb + c * PLANE + rowc);    // staged this/last iter -> L1 hit
                float4 rv = ld_cs4(rb + c * PLANE + rowc); // read-once stream
                float4 o;
                o.x = flip_one(cc.x, J.x, bf.x, rv.x, d0);
                o.y = flip_one(cc.y, J.y, bf.y, rv.y, d1);
                o.z = flip_one(cc.z, J.z, bf.z, rv.z, d2);
                o.w = flip_one(cc.w, J.w, bf.w, rv.w, d3);
                st_cs4(ob + c * PLANE + rowc, o);          // write-once
            }
        }
    }
}

extern "C" void kernel_launch(void* const* d_in, const int* in_sizes, int n_in,
                              void* d_out, int out_size) {
    const float* x    = (const float*)d_in[0];   // (4,9,1024,1024)
    const float* rnd  = (const float*)d_in[1];   // (4,8,1024,1024)
    const float* drop = (const float*)d_in[2];   // (1024,1024)
    // d_in[3] = nn_kernel: fixed cross structure, baked into the kernel
    float* out = (float*)d_out;

    int grid = 4 * SPB;                          // 304 CTAs = 2/SM x 152 SMs, single wave
    ising_step_kernel<<<grid, 512>>>(x, rnd, drop, out);
}